// round 3
// baseline (speedup 1.0000x reference)
#include <cuda_runtime.h>
#include <math.h>

// Problem dims
#define T_STEPS 16384
#define E_DIM   1024
#define H_DIM   1024
#define R_DIM   4096   // 4*H

// Recurrent kernel config
#define NBLK     128   // persistent blocks (<=148 SMs, 1/SM by smem)
#define JPB      8     // h-lanes per block (NBLK*JPB = H_DIM)
#define RTHREADS 256   // 8 warps, 1 warp per h-lane

// GEMM config
#define BM 64
#define BN 64
#define BK 32

// ---------------- device scratch (no allocations allowed) ----------------
__device__ float    g_xg[(size_t)T_STEPS * R_DIM];      // 256 MB input projections
__device__ float    g_hbuf[2][H_DIM];                   // double-buffered hidden state
__device__ float    g_sumexp[(size_t)T_STEPS * NBLK];   // per-(step,block) partial sum(exp(h))
__device__ float    g_hy[T_STEPS];                      // h[y_t] per step
__device__ unsigned g_bar_count;                        // grid barrier arrive counter
__device__ unsigned g_bar_gen;                          // grid barrier generation

// ---------------- kernel 1: xg = Xs @ W_ih^T + b_ih + b_hh ----------------
__global__ void __launch_bounds__(256) xg_gemm(
    const float* __restrict__ Xs, const float* __restrict__ W_ih,
    const float* __restrict__ b_ih, const float* __restrict__ b_hh)
{
    __shared__ float As[BM][BK + 4];
    __shared__ float Bs[BN][BK + 4];

    const int bm  = blockIdx.y * BM;   // timestep tile
    const int bn  = blockIdx.x * BN;   // gate-row tile
    const int tid = threadIdx.x;
    const int tx  = tid & 15;          // 16 x 16 thread grid
    const int ty  = tid >> 4;

    float acc[4][4];
#pragma unroll
    for (int i = 0; i < 4; i++)
#pragma unroll
        for (int jj = 0; jj < 4; jj++) acc[i][jj] = 0.0f;

    for (int k0 = 0; k0 < E_DIM; k0 += BK) {
        // load 64x32 A tile and 64x32 B tile, float4 vectorized
#pragma unroll
        for (int i = 0; i < 2; i++) {
            int idx = tid + i * 256;          // 0..511
            int r   = idx >> 3;               // row 0..63
            int c4  = (idx & 7) << 2;         // col 0..28 step 4
            float4 va = *(const float4*)&Xs[(size_t)(bm + r) * E_DIM + k0 + c4];
            As[r][c4 + 0] = va.x; As[r][c4 + 1] = va.y;
            As[r][c4 + 2] = va.z; As[r][c4 + 3] = va.w;
            float4 vb = *(const float4*)&W_ih[(size_t)(bn + r) * E_DIM + k0 + c4];
            Bs[r][c4 + 0] = vb.x; Bs[r][c4 + 1] = vb.y;
            Bs[r][c4 + 2] = vb.z; Bs[r][c4 + 3] = vb.w;
        }
        __syncthreads();

#pragma unroll
        for (int kk = 0; kk < BK; kk++) {
            float a[4], b[4];
#pragma unroll
            for (int i = 0; i < 4; i++)  a[i]  = As[ty * 4 + i][kk];
#pragma unroll
            for (int jj = 0; jj < 4; jj++) b[jj] = Bs[tx * 4 + jj][kk];
#pragma unroll
            for (int i = 0; i < 4; i++)
#pragma unroll
                for (int jj = 0; jj < 4; jj++)
                    acc[i][jj] += a[i] * b[jj];
        }
        __syncthreads();
    }

#pragma unroll
    for (int i = 0; i < 4; i++) {
        int t = bm + ty * 4 + i;
#pragma unroll
        for (int jj = 0; jj < 4; jj++) {
            int r = bn + tx * 4 + jj;
            g_xg[(size_t)t * R_DIM + r] = acc[i][jj] + __ldg(&b_ih[r]) + __ldg(&b_hh[r]);
        }
    }
}

// ---------------- grid barrier (persistent kernel, NBLK co-resident blocks) ----------------
__device__ __forceinline__ void grid_barrier(unsigned target)
{
    __syncthreads();
    if (threadIdx.x == 0) {
        __threadfence();
        unsigned t = atomicAdd(&g_bar_count, 1u);
        if (t == NBLK - 1) {
            g_bar_count = 0u;
            __threadfence();
            atomicAdd(&g_bar_gen, 1u);
        } else {
            unsigned g;
            do {
                asm volatile("ld.acquire.gpu.u32 %0, [%1];"
                             : "=r"(g) : "l"(&g_bar_gen) : "memory");
            } while ((int)(g - target) < 0);
        }
    }
    __syncthreads();
}

// ---------------- kernel 2: persistent LSTM recurrence ----------------
// Block b owns h-lanes j = b*8 .. b*8+7 (one warp per lane).
// smem: W rows [8 warps][4 gates][1024], staged h [1024], per-warp exp scratch [8]
#define RNN_SMEM ((32 * 1024 + 1024 + 32) * sizeof(float))

__global__ void __launch_bounds__(RTHREADS, 1) lstm_rnn(
    const float* __restrict__ W_hh, const long long* __restrict__ ys)
{
    extern __shared__ float smem[];
    float* Wsm = smem;                 // 32 rows x 1024
    float* hsm = smem + 32 * 1024;     // 1024
    float* red = hsm + 1024;           // 8 (+pad)

    const int tid  = threadIdx.x;
    const int b    = blockIdx.x;
    const int w    = tid >> 5;
    const int lane = tid & 31;
    const int j    = b * JPB + w;

    // Load this block's 32 W_hh rows into smem (rows j, H+j, 2H+j, 3H+j per warp)
#pragma unroll
    for (int r = 0; r < 4; r++) {
        const float* src = W_hh + (size_t)(r * H_DIM + j) * H_DIM;
        float*       dst = Wsm + (size_t)(w * 4 + r) * H_DIM;
        for (int k = lane * 4; k < H_DIM; k += 128) {
            *(float4*)(dst + k) = *(const float4*)(src + k);
        }
    }
    // zero h buffer 0 (h_0 = 0); c_0 = 0 held in registers
    if (tid < JPB) g_hbuf[0][b * JPB + tid] = 0.0f;

    // read barrier generation base (consistent across replays: nobody bumps it
    // until all NBLK blocks have arrived at barrier #1)
    __shared__ unsigned s_gen0;
    if (tid == 0) s_gen0 = atomicAdd(&g_bar_gen, 0u);
    __syncthreads();
    const unsigned gen0 = s_gen0;

    float c_state = 0.0f;
    unsigned nbar = 1;
    grid_barrier(gen0 + nbar);   // h0 + weights visible everywhere

    const float* w0 = Wsm + (size_t)(w * 4 + 0) * H_DIM;
    const float* w1 = Wsm + (size_t)(w * 4 + 1) * H_DIM;
    const float* w2 = Wsm + (size_t)(w * 4 + 2) * H_DIM;
    const float* w3 = Wsm + (size_t)(w * 4 + 3) * H_DIM;

    for (int t = 0; t < T_STEPS; t++) {
        // prefetch xg scalars + label early (DRAM latency hidden under the dots)
        const float* xgp = &g_xg[(size_t)t * R_DIM + j];
        float xg_i = __ldg(xgp + 0 * H_DIM);
        float xg_f = __ldg(xgp + 1 * H_DIM);
        float xg_g = __ldg(xgp + 2 * H_DIM);
        float xg_o = __ldg(xgp + 3 * H_DIM);
        long long y_t = __ldg(&ys[t]);

        // stage h_prev (written by all blocks last step; bypass L1 via ld.cg)
        {
            const float4* src = (const float4*)g_hbuf[t & 1];
            float4 v = __ldcg(&src[tid]);            // 256 * float4 = 1024 floats
            *(float4*)&hsm[tid * 4] = v;
        }
        __syncthreads();

        // 4 dot products of length 1024 per warp (gate rows i,f,g,o for lane j)
        float a0 = 0.f, a1 = 0.f, a2 = 0.f, a3 = 0.f;
#pragma unroll
        for (int i = 0; i < 8; i++) {
            int k = (lane << 2) + (i << 7);          // conflict-free float4 pattern
            float4 hv = *(const float4*)&hsm[k];
            float4 q;
            q = *(const float4*)&w0[k]; a0 += q.x*hv.x + q.y*hv.y + q.z*hv.z + q.w*hv.w;
            q = *(const float4*)&w1[k]; a1 += q.x*hv.x + q.y*hv.y + q.z*hv.z + q.w*hv.w;
            q = *(const float4*)&w2[k]; a2 += q.x*hv.x + q.y*hv.y + q.z*hv.z + q.w*hv.w;
            q = *(const float4*)&w3[k]; a3 += q.x*hv.x + q.y*hv.y + q.z*hv.z + q.w*hv.w;
        }
#pragma unroll
        for (int off = 16; off > 0; off >>= 1) {
            a0 += __shfl_xor_sync(0xffffffffu, a0, off);
            a1 += __shfl_xor_sync(0xffffffffu, a1, off);
            a2 += __shfl_xor_sync(0xffffffffu, a2, off);
            a3 += __shfl_xor_sync(0xffffffffu, a3, off);
        }

        // gates (all lanes hold identical sums after butterfly; redundant compute is free)
        float gi = 1.0f / (1.0f + expf(-(xg_i + a0)));
        float gf = 1.0f / (1.0f + expf(-(xg_f + a1)));
        float gg = tanhf(xg_g + a2);
        float go = 1.0f / (1.0f + expf(-(xg_o + a3)));
        c_state  = gf * c_state + gi * gg;
        float h  = go * tanhf(c_state);

        if (lane == 0) {
            g_hbuf[(t + 1) & 1][j] = h;
            red[w] = expf(h);                         // h in (-1,1): no max-shift needed
            if ((int)y_t == j) g_hy[t] = h;
        }
        __syncthreads();
        if (tid == 0) {
            float s = 0.f;
#pragma unroll
            for (int q = 0; q < JPB; q++) s += red[q];
            g_sumexp[(size_t)t * NBLK + b] = s;
        }

        nbar++;
        grid_barrier(gen0 + nbar);                   // release h(t+1) to everyone
    }
}

// ---------------- kernel 3: deterministic loss reduction ----------------
__global__ void __launch_bounds__(256) loss_reduce(float* __restrict__ out)
{
    __shared__ double sred[256];
    double lsum = 0.0;
    for (int t = threadIdx.x; t < T_STEPS; t += 256) {
        float s = 0.0f;
        const float* p = &g_sumexp[(size_t)t * NBLK];
#pragma unroll 8
        for (int b = 0; b < NBLK; b++) s += p[b];
        lsum += (double)(logf(s) - g_hy[t]);
    }
    sred[threadIdx.x] = lsum;
    __syncthreads();
    for (int off = 128; off > 0; off >>= 1) {
        if (threadIdx.x < off) sred[threadIdx.x] += sred[threadIdx.x + off];
        __syncthreads();
    }
    if (threadIdx.x == 0) out[0] = (float)sred[0];
}

// ---------------- launch ----------------
extern "C" void kernel_launch(void* const* d_in, const int* in_sizes, int n_in,
                              void* d_out, int out_size)
{
    const float*     Xs   = (const float*)d_in[0];
    const float*     W_ih = (const float*)d_in[1];
    const float*     W_hh = (const float*)d_in[2];
    const float*     b_ih = (const float*)d_in[3];
    const float*     b_hh = (const float*)d_in[4];
    const long long* ys   = (const long long*)d_in[5];

    cudaFuncSetAttribute(lstm_rnn, cudaFuncAttributeMaxDynamicSharedMemorySize,
                         (int)RNN_SMEM);

    dim3 g1(R_DIM / BN, T_STEPS / BM);
    xg_gemm<<<g1, 256>>>(Xs, W_ih, b_ih, b_hh);
    lstm_rnn<<<NBLK, RTHREADS, RNN_SMEM>>>(W_hh, ys);
    loss_reduce<<<1, 256>>>((float*)d_out);
}

// round 4
// speedup vs baseline: 1.2143x; 1.2143x over previous
#include <cuda_runtime.h>
#include <math.h>

// Problem dims
#define T_STEPS 16384
#define E_DIM   1024
#define H_DIM   1024
#define R_DIM   4096   // 4*H

// Recurrent kernel config
#define NBLK     128   // persistent blocks (<=148 SMs, 1/SM by smem)
#define JPB      8     // h-lanes per block (NBLK*JPB = H_DIM)
#define RTHREADS 256   // 8 warps, 1 warp per h-lane

// GEMM config
#define BM 64
#define BN 64
#define BK 32

// ---------------- device scratch (no allocations allowed) ----------------
__device__ float    g_xg[(size_t)T_STEPS * R_DIM];      // 256 MB input projections
__device__ float    g_hbuf[2][H_DIM];                   // double-buffered hidden state
__device__ float    g_sumexp[(size_t)T_STEPS * NBLK];   // per-(step,block) partial sum(exp(h))
__device__ float    g_hy[T_STEPS];                      // h[y_t] per step
__device__ unsigned g_flag[NBLK][8];                    // per-block step flags, 32B padded

// ---------------- kernel 1: xg = Xs @ W_ih^T + b_ih + b_hh ----------------
__global__ void __launch_bounds__(256) xg_gemm(
    const float* __restrict__ Xs, const float* __restrict__ W_ih,
    const float* __restrict__ b_ih, const float* __restrict__ b_hh)
{
    __shared__ float As[BM][BK + 4];
    __shared__ float Bs[BN][BK + 4];

    const int bm  = blockIdx.y * BM;   // timestep tile
    const int bn  = blockIdx.x * BN;   // gate-row tile
    const int tid = threadIdx.x;
    const int tx  = tid & 15;          // 16 x 16 thread grid
    const int ty  = tid >> 4;

    float acc[4][4];
#pragma unroll
    for (int i = 0; i < 4; i++)
#pragma unroll
        for (int jj = 0; jj < 4; jj++) acc[i][jj] = 0.0f;

    for (int k0 = 0; k0 < E_DIM; k0 += BK) {
#pragma unroll
        for (int i = 0; i < 2; i++) {
            int idx = tid + i * 256;          // 0..511
            int r   = idx >> 3;               // row 0..63
            int c4  = (idx & 7) << 2;         // col 0..28 step 4
            float4 va = *(const float4*)&Xs[(size_t)(bm + r) * E_DIM + k0 + c4];
            As[r][c4 + 0] = va.x; As[r][c4 + 1] = va.y;
            As[r][c4 + 2] = va.z; As[r][c4 + 3] = va.w;
            float4 vb = *(const float4*)&W_ih[(size_t)(bn + r) * E_DIM + k0 + c4];
            Bs[r][c4 + 0] = vb.x; Bs[r][c4 + 1] = vb.y;
            Bs[r][c4 + 2] = vb.z; Bs[r][c4 + 3] = vb.w;
        }
        __syncthreads();

#pragma unroll
        for (int kk = 0; kk < BK; kk++) {
            float a[4], b[4];
#pragma unroll
            for (int i = 0; i < 4; i++)  a[i]  = As[ty * 4 + i][kk];
#pragma unroll
            for (int jj = 0; jj < 4; jj++) b[jj] = Bs[tx * 4 + jj][kk];
#pragma unroll
            for (int i = 0; i < 4; i++)
#pragma unroll
                for (int jj = 0; jj < 4; jj++)
                    acc[i][jj] += a[i] * b[jj];
        }
        __syncthreads();
    }

#pragma unroll
    for (int i = 0; i < 4; i++) {
        int t = bm + ty * 4 + i;
#pragma unroll
        for (int jj = 0; jj < 4; jj++) {
            int r = bn + tx * 4 + jj;
            g_xg[(size_t)t * R_DIM + r] = acc[i][jj] + __ldg(&b_ih[r]) + __ldg(&b_hh[r]);
        }
    }
}

// ---------------- kernel 2: persistent LSTM recurrence ----------------
// Block b owns h-lanes j = b*8 .. b*8+7 (one warp per lane).
// Sync: per-block release flags; thread tid<128 polls flag[tid] then fetches
// that block's 8 h values (fused detect+fetch, one L2 round-trip).
#define RNN_SMEM ((32 * 1024 + 1024 + 32) * sizeof(float))

__global__ void __launch_bounds__(RTHREADS, 1) lstm_rnn(
    const float* __restrict__ W_hh, const long long* __restrict__ ys)
{
    extern __shared__ float smem[];
    float* Wsm = smem;                 // 32 rows x 1024
    float* hsm = smem + 32 * 1024;     // 1024
    float* red = hsm + 1024;           // 8 (+pad)

    const int tid  = threadIdx.x;
    const int b    = blockIdx.x;
    const int w    = tid >> 5;
    const int lane = tid & 31;
    const int j    = b * JPB + w;

    // Load this block's 32 W_hh rows into smem (rows j, H+j, 2H+j, 3H+j per warp)
#pragma unroll
    for (int r = 0; r < 4; r++) {
        const float* src = W_hh + (size_t)(r * H_DIM + j) * H_DIM;
        float*       dst = Wsm + (size_t)(w * 4 + r) * H_DIM;
        for (int k = lane * 4; k < H_DIM; k += 128) {
            *(float4*)(dst + k) = *(const float4*)(src + k);
        }
    }

    // flag base: only block b ever writes g_flag[b][0]; all flags are uniform
    // at kernel entry (0 first run, base+T after each replay) -> consistent base.
    __shared__ unsigned s_base;
    if (tid == 0) s_base = g_flag[b][0];
    __syncthreads();
    const unsigned base = s_base;

    const float* w0 = Wsm + (size_t)(w * 4 + 0) * H_DIM;
    const float* w1 = Wsm + (size_t)(w * 4 + 1) * H_DIM;
    const float* w2 = Wsm + (size_t)(w * 4 + 2) * H_DIM;
    const float* w3 = Wsm + (size_t)(w * 4 + 3) * H_DIM;

    float c_state = 0.0f;

    for (int t = 0; t < T_STEPS; t++) {
        // prefetch xg scalars + label (LDG latency overlaps the poll below)
        const float* xgp = &g_xg[(size_t)t * R_DIM + j];
        float xg_i = __ldg(xgp + 0 * H_DIM);
        float xg_f = __ldg(xgp + 1 * H_DIM);
        float xg_g = __ldg(xgp + 2 * H_DIM);
        float xg_o = __ldg(xgp + 3 * H_DIM);
        long long y_t = __ldg(&ys[t]);

        // stage h_prev: thread tid<128 waits on producer block tid, then fetches
        if (t == 0) {
            *(float4*)&hsm[tid * 4] = make_float4(0.f, 0.f, 0.f, 0.f);
        } else if (tid < NBLK) {
            const unsigned target = base + (unsigned)t;
            unsigned v;
            do {
                asm volatile("ld.acquire.gpu.u32 %0, [%1];"
                             : "=r"(v) : "l"(&g_flag[tid][0]) : "memory");
            } while ((int)(v - target) < 0);
            const float4* src = (const float4*)&g_hbuf[(t - 1) & 1][tid * JPB];
            float4 h0 = __ldcg(src + 0);
            float4 h1 = __ldcg(src + 1);
            *(float4*)&hsm[tid * JPB + 0] = h0;
            *(float4*)&hsm[tid * JPB + 4] = h1;
        }
        __syncthreads();

        // 4 dot products of length 1024 per warp (gate rows i,f,g,o for lane j)
        float a0 = 0.f, a1 = 0.f, a2 = 0.f, a3 = 0.f;
#pragma unroll
        for (int i = 0; i < 8; i++) {
            int k = (lane << 2) + (i << 7);          // conflict-free float4 pattern
            float4 hv = *(const float4*)&hsm[k];
            float4 q;
            q = *(const float4*)&w0[k]; a0 += q.x*hv.x + q.y*hv.y + q.z*hv.z + q.w*hv.w;
            q = *(const float4*)&w1[k]; a1 += q.x*hv.x + q.y*hv.y + q.z*hv.z + q.w*hv.w;
            q = *(const float4*)&w2[k]; a2 += q.x*hv.x + q.y*hv.y + q.z*hv.z + q.w*hv.w;
            q = *(const float4*)&w3[k]; a3 += q.x*hv.x + q.y*hv.y + q.z*hv.z + q.w*hv.w;
        }
#pragma unroll
        for (int off = 16; off > 0; off >>= 1) {
            a0 += __shfl_xor_sync(0xffffffffu, a0, off);
            a1 += __shfl_xor_sync(0xffffffffu, a1, off);
            a2 += __shfl_xor_sync(0xffffffffu, a2, off);
            a3 += __shfl_xor_sync(0xffffffffu, a3, off);
        }

        float gi = 1.0f / (1.0f + expf(-(xg_i + a0)));
        float gf = 1.0f / (1.0f + expf(-(xg_f + a1)));
        float gg = tanhf(xg_g + a2);
        float go = 1.0f / (1.0f + expf(-(xg_o + a3)));
        c_state  = gf * c_state + gi * gg;
        float h  = go * tanhf(c_state);

        // publish h, then release flag ASAP; sumexp bookkeeping after the flag
        if (lane == 0) {
            g_hbuf[t & 1][j] = h;
            red[w] = expf(h);                         // h in (-1,1): no max-shift needed
            if ((int)y_t == j) g_hy[t] = h;
        }
        __syncthreads();                              // all 8 h writes + red[] done
        if (tid == 0) {
            __threadfence();                          // make h globally visible
            asm volatile("st.release.gpu.u32 [%0], %1;"
                         :: "l"(&g_flag[b][0]), "r"(base + (unsigned)t + 1u)
                         : "memory");
            float s = 0.f;                            // off critical path
#pragma unroll
            for (int q = 0; q < JPB; q++) s += red[q];
            g_sumexp[(size_t)t * NBLK + b] = s;
        }
    }
}

// ---------------- kernel 3: deterministic loss reduction ----------------
__global__ void __launch_bounds__(256) loss_reduce(float* __restrict__ out)
{
    __shared__ double sred[256];
    double lsum = 0.0;
    for (int t = threadIdx.x; t < T_STEPS; t += 256) {
        float s = 0.0f;
        const float* p = &g_sumexp[(size_t)t * NBLK];
#pragma unroll 8
        for (int b = 0; b < NBLK; b++) s += p[b];
        lsum += (double)(logf(s) - g_hy[t]);
    }
    sred[threadIdx.x] = lsum;
    __syncthreads();
    for (int off = 128; off > 0; off >>= 1) {
        if (threadIdx.x < off) sred[threadIdx.x] += sred[threadIdx.x + off];
        __syncthreads();
    }
    if (threadIdx.x == 0) out[0] = (float)sred[0];
}

// ---------------- launch ----------------
extern "C" void kernel_launch(void* const* d_in, const int* in_sizes, int n_in,
                              void* d_out, int out_size)
{
    const float*     Xs   = (const float*)d_in[0];
    const float*     W_ih = (const float*)d_in[1];
    const float*     W_hh = (const float*)d_in[2];
    const float*     b_ih = (const float*)d_in[3];
    const float*     b_hh = (const float*)d_in[4];
    const long long* ys   = (const long long*)d_in[5];

    cudaFuncSetAttribute(lstm_rnn, cudaFuncAttributeMaxDynamicSharedMemorySize,
                         (int)RNN_SMEM);

    dim3 g1(R_DIM / BN, T_STEPS / BM);
    xg_gemm<<<g1, 256>>>(Xs, W_ih, b_ih, b_hh);
    lstm_rnn<<<NBLK, RTHREADS, RNN_SMEM>>>(W_hh, ys);
    loss_reduce<<<1, 256>>>((float*)d_out);
}